// round 2
// baseline (speedup 1.0000x reference)
#include <cuda_runtime.h>

#define B_   2048
#define D_   768
#define E_   5
#define KK   100
#define L_   8
#define EK   500         // E_*KK
#define EPSF 1e-12f

// Scratch (no allocation allowed in kernel_launch)
__device__ float g_M[EK * D_];          // As * Ks / max(||Ks||, eps)
__device__ float g_S[EK * D_];          // As^2
__device__ float g_aq[E_ * B_ * KK];    // normalized attention weights

// ---------------------------------------------------------------------------
// Kernel A: per (e,k) row: norm of Ks, build M and S. 500 blocks x 256 thr.
// ---------------------------------------------------------------------------
__global__ void prep_kernel(const float* __restrict__ Ks,
                            const float* __restrict__ As) {
    int j = blockIdx.x;                     // j = e*KK + k
    const float* kp = Ks + (size_t)j * D_;
    const float* ap = As + (size_t)j * D_;

    float s = 0.f;
    for (int d = threadIdx.x; d < D_; d += 256) {
        float v = kp[d];
        s += v * v;
    }
    #pragma unroll
    for (int o = 16; o > 0; o >>= 1) s += __shfl_xor_sync(0xffffffffu, s, o);

    __shared__ float red[8];
    if ((threadIdx.x & 31) == 0) red[threadIdx.x >> 5] = s;
    __syncthreads();
    float tot = 0.f;
    #pragma unroll
    for (int i = 0; i < 8; i++) tot += red[i];

    float inv = 1.f / fmaxf(sqrtf(tot), EPSF);
    for (int d = threadIdx.x; d < D_; d += 256) {
        float a = ap[d];
        g_M[(size_t)j * D_ + d] = a * kp[d] * inv;
        g_S[(size_t)j * D_ + d] = a * a;
    }
}

// ---------------------------------------------------------------------------
// Kernel B: dual GEMM. num = x @ M^T, den = (x^2) @ S^T over d=768,
// aq = num / max(sqrt(den), eps). Tile 64x64, thread 4x4, Kc=16.
// ---------------------------------------------------------------------------
#define BKC 16

__global__ __launch_bounds__(256) void aq_kernel(const float* __restrict__ x) {
    __shared__ float xs [BKC][64];
    __shared__ float x2s[BKC][64];
    __shared__ float ms [BKC][64];
    __shared__ float ss [BKC][64];

    int bm0 = blockIdx.y * 64;
    int bn0 = blockIdx.x * 64;
    int tid = threadIdx.x;
    int tx = tid & 15, ty = tid >> 4;

    float num[4][4] = {};
    float den[4][4] = {};

    for (int k0 = 0; k0 < D_; k0 += BKC) {
        #pragma unroll
        for (int r = 0; r < 4; r++) {
            int i = tid + 256 * r;
            int row = i >> 4, col = i & 15;
            float v = x[(size_t)(bm0 + row) * D_ + k0 + col];
            xs [col][row] = v;
            x2s[col][row] = v * v;
        }
        #pragma unroll
        for (int r = 0; r < 4; r++) {
            int i = tid + 256 * r;
            int row = i >> 4, col = i & 15;
            int j = bn0 + row;
            float mv = 0.f, sv = 0.f;
            if (j < EK) {
                mv = g_M[(size_t)j * D_ + k0 + col];
                sv = g_S[(size_t)j * D_ + k0 + col];
            }
            ms[col][row] = mv;
            ss[col][row] = sv;
        }
        __syncthreads();

        #pragma unroll
        for (int kc = 0; kc < BKC; kc++) {
            float4 xv  = *(const float4*)&xs [kc][ty * 4];
            float4 x2v = *(const float4*)&x2s[kc][ty * 4];
            float4 mv  = *(const float4*)&ms [kc][tx * 4];
            float4 sv  = *(const float4*)&ss [kc][tx * 4];
            float xa [4] = {xv.x,  xv.y,  xv.z,  xv.w};
            float x2a[4] = {x2v.x, x2v.y, x2v.z, x2v.w};
            float ma [4] = {mv.x,  mv.y,  mv.z,  mv.w};
            float sa [4] = {sv.x,  sv.y,  sv.z,  sv.w};
            #pragma unroll
            for (int i = 0; i < 4; i++)
                #pragma unroll
                for (int jj = 0; jj < 4; jj++) {
                    num[i][jj] += xa[i]  * ma[jj];
                    den[i][jj] += x2a[i] * sa[jj];
                }
        }
        __syncthreads();
    }

    #pragma unroll
    for (int jj = 0; jj < 4; jj++) {
        int j = bn0 + tx * 4 + jj;
        if (j >= EK) continue;
        int e = j / KK, k = j % KK;
        #pragma unroll
        for (int i = 0; i < 4; i++) {
            int b = bm0 + ty * 4 + i;
            float v = num[i][jj] / fmaxf(sqrtf(den[i][jj]), EPSF);
            g_aq[((size_t)e * B_ + b) * KK + k] = v;
        }
    }
}

// ---------------------------------------------------------------------------
// Kernel C: per-expert GEMM  C[b, c] = sum_k aq[e,b,k] * Ps[e,k,c]
//   c = l*768 + d in [0, 6144). Tile 128(M)x64(N), thread 8x4, K=100 in 2x50.
//   Epilogue fuses the keys/values split permutation.
// ---------------------------------------------------------------------------
#define CKC 50
#define AQP 132   // aq smem pitch (128 + 4 pad), 16B-aligned rows

__global__ __launch_bounds__(256) void out_kernel(const float* __restrict__ Ps,
                                                  float* __restrict__ out) {
    __shared__ float aqs[CKC][AQP];   // [k][b], b in tile of 128
    __shared__ float ps [CKC][64];    // [k][c]

    int e   = blockIdx.z;
    int bm0 = blockIdx.y * 128;
    int cn0 = blockIdx.x * 64;
    int tid = threadIdx.x;
    int tx = tid & 15, ty = tid >> 4;   // tx -> N (4 cols), ty -> M (8 rows)

    const float* aqb = g_aq + (size_t)e * B_ * KK;
    const float* psb = Ps   + (size_t)e * KK * (L_ * D_);

    float acc[8][4] = {};

    #pragma unroll
    for (int k0 = 0; k0 < KK; k0 += CKC) {
        for (int i = tid; i < 128 * CKC; i += 256) {
            int b = i / CKC, k = i % CKC;
            aqs[k][b] = aqb[(size_t)(bm0 + b) * KK + k0 + k];
        }
        for (int i = tid; i < CKC * 64; i += 256) {
            int k = i >> 6, c = i & 63;
            ps[k][c] = psb[(size_t)(k0 + k) * (L_ * D_) + cn0 + c];
        }
        __syncthreads();

        #pragma unroll
        for (int k = 0; k < CKC; k++) {
            float4 a0 = *(const float4*)&aqs[k][ty * 8];
            float4 a1 = *(const float4*)&aqs[k][ty * 8 + 4];
            float4 pv = *(const float4*)&ps [k][tx * 4];
            float aa[8] = {a0.x, a0.y, a0.z, a0.w, a1.x, a1.y, a1.z, a1.w};
            float pp[4] = {pv.x, pv.y, pv.z, pv.w};
            #pragma unroll
            for (int i = 0; i < 8; i++)
                #pragma unroll
                for (int jj = 0; jj < 4; jj++)
                    acc[i][jj] += aa[i] * pp[jj];
        }
        __syncthreads();
    }

    // Epilogue with fused keys/values split:
    // c -> (l, d); s = (l>=4); out[((s*E+e)*B + b)*4*768 + (l&3)*768 + d]
    int c0 = cn0 + tx * 4;          // 4 consecutive c, same l (768 % 4 == 0)
    int l  = c0 / D_;
    int d  = c0 % D_;
    int s  = (l >= (L_ / 2)) ? 1 : 0;
    int lp = l & 3;
    size_t obase = (((size_t)(s * E_ + e) * B_) * 4 + lp) * D_ + d;
    #pragma unroll
    for (int i = 0; i < 8; i++) {
        int b = bm0 + ty * 8 + i;
        float4 v = make_float4(acc[i][0], acc[i][1], acc[i][2], acc[i][3]);
        *(float4*)&out[obase + (size_t)b * 4 * D_] = v;
    }
}

// ---------------------------------------------------------------------------
extern "C" void kernel_launch(void* const* d_in, const int* in_sizes, int n_in,
                              void* d_out, int out_size) {
    const float* x  = (const float*)d_in[0];
    const float* Ks = (const float*)d_in[1];
    const float* As = (const float*)d_in[2];
    const float* Ps = (const float*)d_in[3];
    float* out = (float*)d_out;

    prep_kernel<<<EK, 256>>>(Ks, As);

    dim3 gb((EK + 63) / 64, B_ / 64);        // 8 x 32
    aq_kernel<<<gb, 256>>>(x);

    dim3 gc((L_ * D_) / 64, B_ / 128, E_);   // 96 x 16 x 5
    out_kernel<<<gc, 256>>>(Ps, out);
}

// round 3
// speedup vs baseline: 1.6551x; 1.6551x over previous
#include <cuda_runtime.h>
#include <cstdint>

#define B_   2048
#define D_   768
#define E_   5
#define KK   100
#define L_   8
#define EK   500
#define EPSF 1e-12f

// Scratch (no allocation allowed anywhere)
__device__ float g_M[EK * D_];          // tf32-rounded  As*Ks/max(||Ks||,eps)
__device__ float g_S[EK * D_];          // tf32-rounded  As^2
__device__ float g_aq[E_ * B_ * KK];    // tf32-rounded  normalized weights

// ---------------------------------------------------------------------------
__device__ __forceinline__ float cvt_tf32(float x) {
    uint32_t r;
    asm("cvt.rna.tf32.f32 %0, %1;" : "=r"(r) : "f"(x));
    return __uint_as_float(r);
}

__device__ __forceinline__ void mma_tf32(float (&d)[4],
                                         uint32_t a0, uint32_t a1,
                                         uint32_t a2, uint32_t a3,
                                         uint32_t b0, uint32_t b1) {
    asm volatile(
        "mma.sync.aligned.m16n8k8.row.col.f32.tf32.tf32.f32 "
        "{%0,%1,%2,%3},{%4,%5,%6,%7},{%8,%9},{%0,%1,%2,%3};"
        : "+f"(d[0]), "+f"(d[1]), "+f"(d[2]), "+f"(d[3])
        : "r"(a0), "r"(a1), "r"(a2), "r"(a3), "r"(b0), "r"(b1));
}

// ---------------------------------------------------------------------------
// Kernel A: per (e,k) row: norm of Ks, build M and S (tf32-rounded).
// ---------------------------------------------------------------------------
__global__ void prep_kernel(const float* __restrict__ Ks,
                            const float* __restrict__ As) {
    int j = blockIdx.x;
    const float* kp = Ks + (size_t)j * D_;
    const float* ap = As + (size_t)j * D_;

    float s = 0.f;
    for (int d = threadIdx.x; d < D_; d += 256) {
        float v = kp[d];
        s += v * v;
    }
    #pragma unroll
    for (int o = 16; o > 0; o >>= 1) s += __shfl_xor_sync(0xffffffffu, s, o);

    __shared__ float red[8];
    if ((threadIdx.x & 31) == 0) red[threadIdx.x >> 5] = s;
    __syncthreads();
    float tot = 0.f;
    #pragma unroll
    for (int i = 0; i < 8; i++) tot += red[i];

    float inv = 1.f / fmaxf(sqrtf(tot), EPSF);
    for (int d = threadIdx.x; d < D_; d += 256) {
        float a = ap[d];
        g_M[(size_t)j * D_ + d] = cvt_tf32(a * kp[d] * inv);
        g_S[(size_t)j * D_ + d] = cvt_tf32(a * a);
    }
}

// ---------------------------------------------------------------------------
// Kernel B (tf32 MMA): dual GEMM over d=768.
//   num = x @ M^T, den = (x^2) @ S^T, aq = num / max(sqrt(den), eps)
//   CTA tile 128(M) x 64(N), 8 warps in 4x2, warp tile 32x32, BK=32.
// ---------------------------------------------------------------------------
#define AQ_PIT 36   // 36 % 32 == 4 -> conflict-free frag LDS

__global__ __launch_bounds__(256) void aq_mma_kernel(const float* __restrict__ x) {
    __shared__ float xs[128 * AQ_PIT];
    __shared__ float ms[64 * AQ_PIT];
    __shared__ float ss[64 * AQ_PIT];

    int bm0 = blockIdx.y * 128;
    int bn0 = blockIdx.x * 64;
    int tid  = threadIdx.x;
    int warp = tid >> 5, lane = tid & 31;
    int g = lane >> 2, t = lane & 3;
    int wm0 = (warp >> 1) * 32;      // 4 warps along M
    int wn0 = (warp & 1) * 32;       // 2 warps along N

    float num[2][4][4] = {};
    float den[2][4][4] = {};

    for (int k0 = 0; k0 < D_; k0 += 32) {
        // load x tile 128x32 (cvt to tf32-RN)
        #pragma unroll
        for (int it = 0; it < 4; it++) {
            int idx = tid + it * 256;        // 1024 float4
            int r = idx >> 3, c = (idx & 7) * 4;
            float4 v = *(const float4*)&x[(size_t)(bm0 + r) * D_ + k0 + c];
            v.x = cvt_tf32(v.x); v.y = cvt_tf32(v.y);
            v.z = cvt_tf32(v.z); v.w = cvt_tf32(v.w);
            *(float4*)&xs[r * AQ_PIT + c] = v;
        }
        // load M,S tiles 64x32 (already tf32-rounded in gmem)
        #pragma unroll
        for (int it = 0; it < 2; it++) {
            int idx = tid + it * 256;        // 512 float4
            int r = idx >> 3, c = (idx & 7) * 4;
            int j = bn0 + r;
            float4 mv = make_float4(0.f, 0.f, 0.f, 0.f);
            float4 sv = make_float4(0.f, 0.f, 0.f, 0.f);
            if (j < EK) {
                mv = *(const float4*)&g_M[(size_t)j * D_ + k0 + c];
                sv = *(const float4*)&g_S[(size_t)j * D_ + k0 + c];
            }
            *(float4*)&ms[r * AQ_PIT + c] = mv;
            *(float4*)&ss[r * AQ_PIT + c] = sv;
        }
        __syncthreads();

        #pragma unroll
        for (int ks = 0; ks < 4; ks++) {
            int kk = ks * 8;
            // A fragments (x) + squared versions
            uint32_t ax[2][4], ax2[2][4];
            #pragma unroll
            for (int fm = 0; fm < 2; fm++) {
                int r0 = wm0 + fm * 16 + g;
                float f0 = xs[r0 * AQ_PIT + kk + t];
                float f1 = xs[(r0 + 8) * AQ_PIT + kk + t];
                float f2 = xs[r0 * AQ_PIT + kk + t + 4];
                float f3 = xs[(r0 + 8) * AQ_PIT + kk + t + 4];
                ax[fm][0] = __float_as_uint(f0);
                ax[fm][1] = __float_as_uint(f1);
                ax[fm][2] = __float_as_uint(f2);
                ax[fm][3] = __float_as_uint(f3);
                ax2[fm][0] = __float_as_uint(cvt_tf32(f0 * f0));
                ax2[fm][1] = __float_as_uint(cvt_tf32(f1 * f1));
                ax2[fm][2] = __float_as_uint(cvt_tf32(f2 * f2));
                ax2[fm][3] = __float_as_uint(cvt_tf32(f3 * f3));
            }
            #pragma unroll
            for (int fn = 0; fn < 4; fn++) {
                int n0 = wn0 + fn * 8 + g;
                uint32_t bm0r = __float_as_uint(ms[n0 * AQ_PIT + kk + t]);
                uint32_t bm1r = __float_as_uint(ms[n0 * AQ_PIT + kk + t + 4]);
                uint32_t bs0r = __float_as_uint(ss[n0 * AQ_PIT + kk + t]);
                uint32_t bs1r = __float_as_uint(ss[n0 * AQ_PIT + kk + t + 4]);
                #pragma unroll
                for (int fm = 0; fm < 2; fm++) {
                    mma_tf32(num[fm][fn], ax[fm][0], ax[fm][1], ax[fm][2], ax[fm][3], bm0r, bm1r);
                    mma_tf32(den[fm][fn], ax2[fm][0], ax2[fm][1], ax2[fm][2], ax2[fm][3], bs0r, bs1r);
                }
            }
        }
        __syncthreads();
    }

    // epilogue: normalize and store (tf32-rounded for the next GEMM)
    #pragma unroll
    for (int fm = 0; fm < 2; fm++) {
        int mrow = bm0 + wm0 + fm * 16 + g;
        #pragma unroll
        for (int fn = 0; fn < 4; fn++) {
            int j0 = bn0 + wn0 + fn * 8 + t * 2;
            #pragma unroll
            for (int c = 0; c < 4; c++) {
                int b = mrow + (c >> 1) * 8;
                int j = j0 + (c & 1);
                if (j < EK) {
                    float v = num[fm][fn][c] / fmaxf(sqrtf(den[fm][fn][c]), EPSF);
                    int e = j / KK, k = j % KK;
                    g_aq[((size_t)e * B_ + b) * KK + k] = cvt_tf32(v);
                }
            }
        }
    }
}

// ---------------------------------------------------------------------------
// Kernel C (tf32 MMA): per-expert GEMM C[b,c] = sum_k aq[e,b,k]*Ps[e,k,c]
//   CTA tile 128(M) x 128(N), whole K=100 (pad 104) in smem, single pass.
//   8 warps in 2x4, warp tile 64x32. Fused output split permutation.
// ---------------------------------------------------------------------------
#define O_KP 104
#define O_AP 132   // 132 % 32 == 4 -> A frag conflict-free
#define O_BP 136   // 136 % 32 == 8 -> B frag conflict-free
#define O_SMEM ((128 * O_AP + O_KP * O_BP) * 4)

__global__ __launch_bounds__(256) void out_mma_kernel(const float* __restrict__ Ps,
                                                      float* __restrict__ out) {
    extern __shared__ float sm[];
    float* As = sm;                    // [128][O_AP]
    float* Bs = sm + 128 * O_AP;       // [O_KP][O_BP]

    int e   = blockIdx.z;
    int bm0 = blockIdx.y * 128;
    int cn0 = blockIdx.x * 128;
    int tid  = threadIdx.x;
    int warp = tid >> 5, lane = tid & 31;
    int g = lane >> 2, t = lane & 3;
    int wm0 = (warp >> 2) * 64;        // 2 warps along M
    int wn0 = (warp & 3) * 32;         // 4 warps along N

    const float* aqb = g_aq + (size_t)e * B_ * KK;
    const float* psb = Ps   + (size_t)e * KK * (L_ * D_);

    // Load A: 128 x 104 (aq already tf32-rounded; pad k>=100 with 0)
    for (int i = tid; i < 128 * O_KP; i += 256) {
        int m = i / O_KP, k = i % O_KP;
        As[m * O_AP + k] = (k < KK) ? aqb[(size_t)(bm0 + m) * KK + k] : 0.f;
    }
    // Load B: 104 x 128 (cvt to tf32-RN; pad rows k>=100 with 0)
    for (int i = tid; i < O_KP * 128; i += 256) {
        int k = i >> 7, n = i & 127;
        float v = (k < KK) ? cvt_tf32(psb[(size_t)k * (L_ * D_) + cn0 + n]) : 0.f;
        Bs[k * O_BP + n] = v;
    }
    __syncthreads();

    float acc[4][4][4] = {};

    #pragma unroll
    for (int ks = 0; ks < 13; ks++) {
        int kk = ks * 8;
        uint32_t a[4][4];
        #pragma unroll
        for (int fm = 0; fm < 4; fm++) {
            int r0 = wm0 + fm * 16 + g;
            a[fm][0] = __float_as_uint(As[r0 * O_AP + kk + t]);
            a[fm][1] = __float_as_uint(As[(r0 + 8) * O_AP + kk + t]);
            a[fm][2] = __float_as_uint(As[r0 * O_AP + kk + t + 4]);
            a[fm][3] = __float_as_uint(As[(r0 + 8) * O_AP + kk + t + 4]);
        }
        #pragma unroll
        for (int fn = 0; fn < 4; fn++) {
            int n0 = wn0 + fn * 8 + g;
            uint32_t b0 = __float_as_uint(Bs[(kk + t) * O_BP + n0]);
            uint32_t b1 = __float_as_uint(Bs[(kk + t + 4) * O_BP + n0]);
            #pragma unroll
            for (int fm = 0; fm < 4; fm++)
                mma_tf32(acc[fm][fn], a[fm][0], a[fm][1], a[fm][2], a[fm][3], b0, b1);
        }
    }

    // Epilogue: fused keys/values split.
    // col c -> (l, d); s=(l>=4); out[((s*E+e)*B + b)*4*768 + (l&3)*768 + d]
    #pragma unroll
    for (int fn = 0; fn < 4; fn++) {
        int c = cn0 + wn0 + fn * 8 + t * 2;   // even; pair (c, c+1) same l
        int l  = c / D_;
        int d  = c % D_;
        int s  = (l >= (L_ / 2)) ? 1 : 0;
        int lp = l & 3;
        size_t obase = (((size_t)(s * E_ + e) * B_) * 4 + lp) * D_ + d;
        #pragma unroll
        for (int fm = 0; fm < 4; fm++) {
            int m0 = bm0 + wm0 + fm * 16 + g;
            float2 v0 = make_float2(acc[fm][fn][0], acc[fm][fn][1]);
            float2 v1 = make_float2(acc[fm][fn][2], acc[fm][fn][3]);
            *(float2*)&out[obase + (size_t)m0 * 4 * D_]       = v0;
            *(float2*)&out[obase + (size_t)(m0 + 8) * 4 * D_] = v1;
        }
    }
}

// ---------------------------------------------------------------------------
extern "C" void kernel_launch(void* const* d_in, const int* in_sizes, int n_in,
                              void* d_out, int out_size) {
    const float* x  = (const float*)d_in[0];
    const float* Ks = (const float*)d_in[1];
    const float* As = (const float*)d_in[2];
    const float* Ps = (const float*)d_in[3];
    float* out = (float*)d_out;

    cudaFuncSetAttribute(out_mma_kernel,
                         cudaFuncAttributeMaxDynamicSharedMemorySize, O_SMEM);

    prep_kernel<<<EK, 256>>>(Ks, As);

    dim3 gb(512 / 64, B_ / 128);                 // 8 x 16
    aq_mma_kernel<<<gb, 256>>>(x);

    dim3 gc((L_ * D_) / 128, B_ / 128, E_);      // 48 x 16 x 5
    out_mma_kernel<<<gc, 256, O_SMEM>>>(Ps, out);
}

// round 6
// speedup vs baseline: 3.0123x; 1.8200x over previous
#include <cuda_runtime.h>
#include <cstdint>

#define B_   2048
#define D_   768
#define E_   5
#define KK   100
#define L_   8
#define EK   500
#define NOUT (L_ * D_)          // 6144
#define EPSF 1e-12f

// Scratch (no allocation allowed anywhere)
__device__ float g_M[EK * D_];            // tf32-rounded  As*Ks/max(||Ks||,eps)
__device__ float g_S[EK * D_];            // tf32-rounded  As^2
__device__ float g_aq[E_ * B_ * KK];      // tf32-rounded  normalized weights
__device__ float g_Pr[E_ * KK * NOUT];    // tf32-rounded  Ps

// ---------------------------------------------------------------------------
__device__ __forceinline__ float cvt_tf32(float x) {
    uint32_t r;
    asm("cvt.rna.tf32.f32 %0, %1;" : "=r"(r) : "f"(x));
    return __uint_as_float(r);
}

__device__ __forceinline__ void mma_tf32(float (&d)[4],
                                         uint32_t a0, uint32_t a1,
                                         uint32_t a2, uint32_t a3,
                                         uint32_t b0, uint32_t b1) {
    asm volatile(
        "mma.sync.aligned.m16n8k8.row.col.f32.tf32.tf32.f32 "
        "{%0,%1,%2,%3},{%4,%5,%6,%7},{%8,%9},{%0,%1,%2,%3};"
        : "+f"(d[0]), "+f"(d[1]), "+f"(d[2]), "+f"(d[3])
        : "r"(a0), "r"(a1), "r"(a2), "r"(a3), "r"(b0), "r"(b1));
}

__device__ __forceinline__ uint32_t smem_u32(const void* p) {
    return (uint32_t)__cvta_generic_to_shared(p);
}

__device__ __forceinline__ void cp_async16(uint32_t dst, const void* src, int nbytes) {
    asm volatile("cp.async.cg.shared.global [%0], [%1], 16, %2;\n"
                 :: "r"(dst), "l"(src), "r"(nbytes));
}
#define CP_COMMIT() asm volatile("cp.async.commit_group;\n" ::: "memory")
#define CP_WAIT1()  asm volatile("cp.async.wait_group 1;\n" ::: "memory")

// ---------------------------------------------------------------------------
// Kernel A: per (e,k) row: norm of Ks, build M and S (tf32-rounded).
// ---------------------------------------------------------------------------
__global__ void prep_kernel(const float* __restrict__ Ks,
                            const float* __restrict__ As) {
    int j = blockIdx.x;
    const float* kp = Ks + (size_t)j * D_;
    const float* ap = As + (size_t)j * D_;

    float s = 0.f;
    for (int d = threadIdx.x; d < D_; d += 256) {
        float v = kp[d];
        s += v * v;
    }
    #pragma unroll
    for (int o = 16; o > 0; o >>= 1) s += __shfl_xor_sync(0xffffffffu, s, o);

    __shared__ float red[8];
    if ((threadIdx.x & 31) == 0) red[threadIdx.x >> 5] = s;
    __syncthreads();
    float tot = 0.f;
    #pragma unroll
    for (int i = 0; i < 8; i++) tot += red[i];

    float inv = 1.f / fmaxf(sqrtf(tot), EPSF);
    for (int d = threadIdx.x; d < D_; d += 256) {
        float a = ap[d];
        g_M[(size_t)j * D_ + d] = cvt_tf32(a * kp[d] * inv);
        g_S[(size_t)j * D_ + d] = cvt_tf32(a * a);
    }
}

// ---------------------------------------------------------------------------
// Kernel A2: elementwise tf32-RNA rounding of Ps into g_Pr (float4).
// ---------------------------------------------------------------------------
__global__ void pround_kernel(const float* __restrict__ Ps) {
    int i = (blockIdx.x * 256 + threadIdx.x);   // float4 index
    float4 v = ((const float4*)Ps)[i];
    v.x = cvt_tf32(v.x); v.y = cvt_tf32(v.y);
    v.z = cvt_tf32(v.z); v.w = cvt_tf32(v.w);
    ((float4*)g_Pr)[i] = v;
}

// ---------------------------------------------------------------------------
// Kernel B (tf32 MMA): dual GEMM over d=768.
//   num = x @ M^T, den = (x^2) @ S^T, aq = num / max(sqrt(den), eps)
//   CTA tile 128(M) x 64(N), 8 warps in 4x2, warp tile 32x32, BK=32.
// ---------------------------------------------------------------------------
#define AQ_PIT 36   // 36 % 32 == 4 -> conflict-free frag LDS

__global__ __launch_bounds__(256) void aq_mma_kernel(const float* __restrict__ x) {
    __shared__ float xs[128 * AQ_PIT];
    __shared__ float ms[64 * AQ_PIT];
    __shared__ float ss[64 * AQ_PIT];

    int bm0 = blockIdx.y * 128;
    int bn0 = blockIdx.x * 64;
    int tid  = threadIdx.x;
    int warp = tid >> 5, lane = tid & 31;
    int g = lane >> 2, t = lane & 3;
    int wm0 = (warp >> 1) * 32;      // 4 warps along M
    int wn0 = (warp & 1) * 32;       // 2 warps along N

    float num[2][4][4] = {};
    float den[2][4][4] = {};

    for (int k0 = 0; k0 < D_; k0 += 32) {
        #pragma unroll
        for (int it = 0; it < 4; it++) {
            int idx = tid + it * 256;
            int r = idx >> 3, c = (idx & 7) * 4;
            float4 v = *(const float4*)&x[(size_t)(bm0 + r) * D_ + k0 + c];
            v.x = cvt_tf32(v.x); v.y = cvt_tf32(v.y);
            v.z = cvt_tf32(v.z); v.w = cvt_tf32(v.w);
            *(float4*)&xs[r * AQ_PIT + c] = v;
        }
        #pragma unroll
        for (int it = 0; it < 2; it++) {
            int idx = tid + it * 256;
            int r = idx >> 3, c = (idx & 7) * 4;
            int j = bn0 + r;
            float4 mv = make_float4(0.f, 0.f, 0.f, 0.f);
            float4 sv = make_float4(0.f, 0.f, 0.f, 0.f);
            if (j < EK) {
                mv = *(const float4*)&g_M[(size_t)j * D_ + k0 + c];
                sv = *(const float4*)&g_S[(size_t)j * D_ + k0 + c];
            }
            *(float4*)&ms[r * AQ_PIT + c] = mv;
            *(float4*)&ss[r * AQ_PIT + c] = sv;
        }
        __syncthreads();

        #pragma unroll
        for (int ks = 0; ks < 4; ks++) {
            int kk = ks * 8;
            uint32_t ax[2][4], ax2[2][4];
            #pragma unroll
            for (int fm = 0; fm < 2; fm++) {
                int r0 = wm0 + fm * 16 + g;
                float f0 = xs[r0 * AQ_PIT + kk + t];
                float f1 = xs[(r0 + 8) * AQ_PIT + kk + t];
                float f2 = xs[r0 * AQ_PIT + kk + t + 4];
                float f3 = xs[(r0 + 8) * AQ_PIT + kk + t + 4];
                ax[fm][0] = __float_as_uint(f0);
                ax[fm][1] = __float_as_uint(f1);
                ax[fm][2] = __float_as_uint(f2);
                ax[fm][3] = __float_as_uint(f3);
                ax2[fm][0] = __float_as_uint(cvt_tf32(f0 * f0));
                ax2[fm][1] = __float_as_uint(cvt_tf32(f1 * f1));
                ax2[fm][2] = __float_as_uint(cvt_tf32(f2 * f2));
                ax2[fm][3] = __float_as_uint(cvt_tf32(f3 * f3));
            }
            #pragma unroll
            for (int fn = 0; fn < 4; fn++) {
                int n0 = wn0 + fn * 8 + g;
                uint32_t bm0r = __float_as_uint(ms[n0 * AQ_PIT + kk + t]);
                uint32_t bm1r = __float_as_uint(ms[n0 * AQ_PIT + kk + t + 4]);
                uint32_t bs0r = __float_as_uint(ss[n0 * AQ_PIT + kk + t]);
                uint32_t bs1r = __float_as_uint(ss[n0 * AQ_PIT + kk + t + 4]);
                #pragma unroll
                for (int fm = 0; fm < 2; fm++) {
                    mma_tf32(num[fm][fn], ax[fm][0], ax[fm][1], ax[fm][2], ax[fm][3], bm0r, bm1r);
                    mma_tf32(den[fm][fn], ax2[fm][0], ax2[fm][1], ax2[fm][2], ax2[fm][3], bs0r, bs1r);
                }
            }
        }
        __syncthreads();
    }

    #pragma unroll
    for (int fm = 0; fm < 2; fm++) {
        int mrow = bm0 + wm0 + fm * 16 + g;
        #pragma unroll
        for (int fn = 0; fn < 4; fn++) {
            int j0 = bn0 + wn0 + fn * 8 + t * 2;
            #pragma unroll
            for (int c = 0; c < 4; c++) {
                int b = mrow + (c >> 1) * 8;
                int j = j0 + (c & 1);
                if (j < EK) {
                    float v = num[fm][fn][c] / fmaxf(sqrtf(den[fm][fn][c]), EPSF);
                    int e = j / KK, k = j % KK;
                    g_aq[((size_t)e * B_ + b) * KK + k] = cvt_tf32(v);
                }
            }
        }
    }
}

// ---------------------------------------------------------------------------
// Kernel C (tf32 MMA, cp.async pipelined): C[b,c] = sum_k aq[e,b,k]*Pr[e,k,c]
//   CTA tile 128(M) x 128(N); K padded 100->128, 4 chunks of 32, 2-stage
//   double buffer via cp.async zero-fill (src clamped in-bounds).
//   8 warps (2 M x 4 N), warp 64x32.
// ---------------------------------------------------------------------------
#define O_AP 36    // A pitch: 36 % 32 == 4 -> conflict-free
#define O_BP 136   // B pitch: 136 % 32 == 8 -> conflict-free
#define O_ABUF (128 * O_AP)
#define O_BBUF (32 * O_BP)
#define O_SMEM ((2 * O_ABUF + 2 * O_BBUF) * 4)

__global__ __launch_bounds__(256) void out_mma_kernel(float* __restrict__ out) {
    extern __shared__ float sm[];
    float* Asm = sm;                    // [2][128][O_AP]
    float* Bsm = sm + 2 * O_ABUF;       // [2][32][O_BP]

    int e   = blockIdx.z;
    int bm0 = blockIdx.y * 128;
    int cn0 = blockIdx.x * 128;
    int tid  = threadIdx.x;
    int warp = tid >> 5, lane = tid & 31;
    int g = lane >> 2, t = lane & 3;
    int wm0 = (warp >> 2) * 64;        // 2 warps along M
    int wn0 = (warp & 3) * 32;         // 4 warps along N

    const float* aqb = g_aq + (size_t)e * B_ * KK;
    const float* prb = g_Pr + (size_t)e * KK * NOUT;

    // thread mapping for loads
    int arow = tid >> 3;               // 0..31 (A: +it*32 -> 128 rows)
    int acol = (tid & 7) * 4;          // 0..28
    int bk   = tid >> 3;               // 0..31 (B: k within chunk)
    int bn   = (tid & 7) * 16;         // 0..112 (B: 4 float4 each)

    // ---- prefetch chunk 0 ----
    {
        int k0 = 0;
        #pragma unroll
        for (int it = 0; it < 4; it++) {
            int r = arow + it * 32;
            int nb = (k0 + acol < KK) ? 16 : 0;
            int kc = nb ? (k0 + acol) : 0;               // clamp OOB src
            cp_async16(smem_u32(&Asm[r * O_AP + acol]),
                       aqb + (size_t)(bm0 + r) * KK + kc, nb);
        }
        int nbB = (k0 + bk < KK) ? 16 : 0;
        int kB  = nbB ? (k0 + bk) : 0;                   // clamp OOB src
        const float* bsrc = prb + (size_t)kB * NOUT + cn0 + bn;
        #pragma unroll
        for (int j = 0; j < 4; j++)
            cp_async16(smem_u32(&Bsm[bk * O_BP + bn + j * 4]), bsrc + j * 4, nbB);
    }
    CP_COMMIT();

    float acc[4][4][4] = {};
    int buf = 0;

    #pragma unroll
    for (int ch = 0; ch < 4; ch++) {
        // prefetch next chunk into the other buffer
        if (ch + 1 < 4) {
            int k0 = (ch + 1) * 32;
            float* Ad = Asm + (buf ^ 1) * O_ABUF;
            float* Bd = Bsm + (buf ^ 1) * O_BBUF;
            #pragma unroll
            for (int it = 0; it < 4; it++) {
                int r = arow + it * 32;
                int nb = (k0 + acol < KK) ? 16 : 0;
                int kc = nb ? (k0 + acol) : 0;           // clamp OOB src
                cp_async16(smem_u32(&Ad[r * O_AP + acol]),
                           aqb + (size_t)(bm0 + r) * KK + kc, nb);
            }
            int nbB = (k0 + bk < KK) ? 16 : 0;
            int kB  = nbB ? (k0 + bk) : 0;               // clamp OOB src
            const float* bsrc = prb + (size_t)kB * NOUT + cn0 + bn;
            #pragma unroll
            for (int j = 0; j < 4; j++)
                cp_async16(smem_u32(&Bd[bk * O_BP + bn + j * 4]), bsrc + j * 4, nbB);
        }
        CP_COMMIT();
        CP_WAIT1();              // current chunk's group has landed
        __syncthreads();

        const float* Ac = Asm + buf * O_ABUF;
        const float* Bc = Bsm + buf * O_BBUF;

        #pragma unroll
        for (int ks = 0; ks < 4; ks++) {
            int kk = ks * 8;
            uint32_t a[4][4];
            #pragma unroll
            for (int fm = 0; fm < 4; fm++) {
                int r0 = wm0 + fm * 16 + g;
                a[fm][0] = __float_as_uint(Ac[r0 * O_AP + kk + t]);
                a[fm][1] = __float_as_uint(Ac[(r0 + 8) * O_AP + kk + t]);
                a[fm][2] = __float_as_uint(Ac[r0 * O_AP + kk + t + 4]);
                a[fm][3] = __float_as_uint(Ac[(r0 + 8) * O_AP + kk + t + 4]);
            }
            #pragma unroll
            for (int fn = 0; fn < 4; fn++) {
                int n0 = wn0 + fn * 8 + g;
                uint32_t b0 = __float_as_uint(Bc[(kk + t) * O_BP + n0]);
                uint32_t b1 = __float_as_uint(Bc[(kk + t + 4) * O_BP + n0]);
                #pragma unroll
                for (int fm = 0; fm < 4; fm++)
                    mma_tf32(acc[fm][fn], a[fm][0], a[fm][1], a[fm][2], a[fm][3], b0, b1);
            }
        }
        __syncthreads();
        buf ^= 1;
    }

    // Epilogue: fused keys/values split.
    // col c -> (l, d); s=(l>=4); out[((s*E+e)*B + b)*4*768 + (l&3)*768 + d]
    #pragma unroll
    for (int fn = 0; fn < 4; fn++) {
        int c = cn0 + wn0 + fn * 8 + t * 2;   // even; pair (c, c+1) same l
        int l  = c / D_;
        int d  = c % D_;
        int s  = (l >= (L_ / 2)) ? 1 : 0;
        int lp = l & 3;
        size_t obase = (((size_t)(s * E_ + e) * B_) * 4 + lp) * D_ + d;
        #pragma unroll
        for (int fm = 0; fm < 4; fm++) {
            int m0 = bm0 + wm0 + fm * 16 + g;
            float2 v0 = make_float2(acc[fm][fn][0], acc[fm][fn][1]);
            float2 v1 = make_float2(acc[fm][fn][2], acc[fm][fn][3]);
            *(float2*)&out[obase + (size_t)m0 * 4 * D_]       = v0;
            *(float2*)&out[obase + (size_t)(m0 + 8) * 4 * D_] = v1;
        }
    }
}

// ---------------------------------------------------------------------------
extern "C" void kernel_launch(void* const* d_in, const int* in_sizes, int n_in,
                              void* d_out, int out_size) {
    const float* x  = (const float*)d_in[0];
    const float* Ks = (const float*)d_in[1];
    const float* As = (const float*)d_in[2];
    const float* Ps = (const float*)d_in[3];
    float* out = (float*)d_out;

    cudaFuncSetAttribute(out_mma_kernel,
                         cudaFuncAttributeMaxDynamicSharedMemorySize, O_SMEM);

    prep_kernel<<<EK, 256>>>(Ks, As);
    pround_kernel<<<(E_ * KK * NOUT) / (256 * 4), 256>>>(Ps);

    dim3 gb(512 / 64, B_ / 128);                 // 8 x 16
    aq_mma_kernel<<<gb, 256>>>(x);

    dim3 gc(NOUT / 128, B_ / 128, E_);           // 48 x 16 x 5
    out_mma_kernel<<<gc, 256, O_SMEM>>>(out);
}